// round 1
// baseline (speedup 1.0000x reference)
#include <cuda_runtime.h>

#define BATCH 1024
#define MF 1024     // OUT_FEATURES
#define NF 512      // IN_FEATURES
#define LAMBDv 0.2f
#define TOL2 1e-8f  // (1e-4)^2
#define MAX_ITERS 100

#define BM 64
#define BN 64
#define BK 16

// ---------------- scratch (device globals; no allocation allowed) ----------------
__device__ __align__(256) float g_Adb[BATCH * MF];
__device__ __align__(256) float g_u[2][BATCH * MF];
__device__ __align__(256) float g_v[2][BATCH * MF];
__device__ __align__(256) float g_dx2p[BATCH * 16];
__device__ __align__(256) float g_x2p[BATCH * 16];
__device__ int g_solved[BATCH];
__device__ int g_idx[BATCH];
__device__ int g_nact;

// ---------------- init: zero state + encoded output, reset flags ----------------
__global__ void init_kernel(float* __restrict__ enc) {
    int i = blockIdx.x * blockDim.x + threadIdx.x;  // 0 .. BATCH*MF/4-1
    float4 z = make_float4(0.f, 0.f, 0.f, 0.f);
    ((float4*)g_u[0])[i] = z;
    ((float4*)g_v[0])[i] = z;
    ((float4*)enc)[i] = z;
    if (i < BATCH) { g_solved[i] = 0; g_idx[i] = i; }
    if (i == 0) g_nact = BATCH;
}

// ---------------- A_dot_b = x @ W^T : C[r,n] = sum_k X[r,k]*W[n,k] ----------------
__global__ void gemm_nt_kernel(const float* __restrict__ X, const float* __restrict__ W) {
    __shared__ float As[BK][BM];
    __shared__ float Bs[BK][BN];
    int tid = threadIdx.x;
    int row0 = blockIdx.y * BM, col0 = blockIdx.x * BN;
    int lr = tid >> 2, kq = tid & 3;
    int tm = tid >> 4, tn = tid & 15;
    float acc[4][4] = {};
    for (int k0 = 0; k0 < NF; k0 += BK) {
        float4 a4 = *(const float4*)(X + (size_t)(row0 + lr) * NF + k0 + kq * 4);
        float4 b4 = *(const float4*)(W + (size_t)(col0 + lr) * NF + k0 + kq * 4);
        __syncthreads();
        As[kq * 4 + 0][lr] = a4.x; As[kq * 4 + 1][lr] = a4.y;
        As[kq * 4 + 2][lr] = a4.z; As[kq * 4 + 3][lr] = a4.w;
        Bs[kq * 4 + 0][lr] = b4.x; Bs[kq * 4 + 1][lr] = b4.y;
        Bs[kq * 4 + 2][lr] = b4.z; Bs[kq * 4 + 3][lr] = b4.w;
        __syncthreads();
#pragma unroll
        for (int kk = 0; kk < BK; kk++) {
            float4 av = *(const float4*)&As[kk][tm * 4];
            float4 bv = *(const float4*)&Bs[kk][tn * 4];
            float a[4] = {av.x, av.y, av.z, av.w};
            float b[4] = {bv.x, bv.y, bv.z, bv.w};
#pragma unroll
            for (int i = 0; i < 4; i++)
#pragma unroll
                for (int j = 0; j < 4; j++) acc[i][j] += a[i] * b[j];
        }
    }
#pragma unroll
    for (int i = 0; i < 4; i++) {
        float4 o = make_float4(acc[i][0], acc[i][1], acc[i][2], acc[i][3]);
        *(float4*)(g_Adb + (size_t)(row0 + tm * 4 + i) * MF + col0 + tn * 4) = o;
    }
}

// ---------------- main iteration GEMM + fused ADMM epilogue ----------------
// xk = (A_dot_b + v - u) @ M_inv on active (compacted) rows only.
// reads parity p, writes parity p^1. Deterministic per-row norm partials.
__global__ void gemm_update_kernel(const float* __restrict__ Minv, int p) {
    int n_act = g_nact;
    int row0 = blockIdx.y * BM;
    if (row0 >= n_act) return;
    int col0 = blockIdx.x * BN;

    __shared__ float As[2][BK][BM];
    __shared__ float Bs[2][BK][BN];
    __shared__ int rowidx[BM];
    __shared__ float red_dx[BM][17];
    __shared__ float red_x2[BM][17];

    int tid = threadIdx.x;
    if (tid < BM) {
        int i = row0 + tid;
        rowidx[tid] = (i < n_act) ? g_idx[i] : -1;
    }
    __syncthreads();

    int lr = tid >> 2, kq = tid & 3;       // A-load mapping
    int kr = tid >> 4, nq = tid & 15;      // B-load mapping
    int tm = tid >> 4, tn = tid & 15;      // compute mapping

    int rA = rowidx[lr];
    const float* adbp = g_Adb + (size_t)rA * MF + kq * 4;
    const float* up = g_u[p] + (size_t)rA * MF + kq * 4;
    const float* vp = g_v[p] + (size_t)rA * MF + kq * 4;
    const float* bp = Minv + (size_t)kr * MF + col0 + nq * 4;

    float4 ra = make_float4(0, 0, 0, 0), rv = ra, ru = ra, rb;
    if (rA >= 0) {
        ra = *(const float4*)(adbp);
        rv = *(const float4*)(vp);
        ru = *(const float4*)(up);
    }
    rb = *(const float4*)(bp);
    As[0][kq * 4 + 0][lr] = ra.x + rv.x - ru.x;
    As[0][kq * 4 + 1][lr] = ra.y + rv.y - ru.y;
    As[0][kq * 4 + 2][lr] = ra.z + rv.z - ru.z;
    As[0][kq * 4 + 3][lr] = ra.w + rv.w - ru.w;
    *(float4*)&Bs[0][kr][nq * 4] = rb;
    __syncthreads();

    float acc[4][4] = {};
    const int NKT = MF / BK;  // 64
    for (int t = 0; t < NKT; t++) {
        int cb = t & 1;
        if (t + 1 < NKT) {
            int off = (t + 1) * BK;
            if (rA >= 0) {
                ra = *(const float4*)(adbp + off);
                rv = *(const float4*)(vp + off);
                ru = *(const float4*)(up + off);
            }
            rb = *(const float4*)(bp + (size_t)off * MF);
        }
#pragma unroll
        for (int kk = 0; kk < BK; kk++) {
            float4 av = *(const float4*)&As[cb][kk][tm * 4];
            float4 bv = *(const float4*)&Bs[cb][kk][tn * 4];
            float a[4] = {av.x, av.y, av.z, av.w};
            float b[4] = {bv.x, bv.y, bv.z, bv.w};
#pragma unroll
            for (int i = 0; i < 4; i++)
#pragma unroll
                for (int j = 0; j < 4; j++) acc[i][j] += a[i] * b[j];
        }
        if (t + 1 < NKT) {
            int nb = cb ^ 1;
            As[nb][kq * 4 + 0][lr] = ra.x + rv.x - ru.x;
            As[nb][kq * 4 + 1][lr] = ra.y + rv.y - ru.y;
            As[nb][kq * 4 + 2][lr] = ra.z + rv.z - ru.z;
            As[nb][kq * 4 + 3][lr] = ra.w + rv.w - ru.w;
            *(float4*)&Bs[nb][kr][nq * 4] = rb;
        }
        __syncthreads();
    }

    // fused ADMM epilogue
    const float* uo_buf = g_u[p];
    float* un_buf = g_u[p ^ 1];
    const float* vo_buf = g_v[p];
    float* vn_buf = g_v[p ^ 1];
#pragma unroll
    for (int i = 0; i < 4; i++) {
        int lrow = tm * 4 + i;
        int rr = rowidx[lrow];
        float ldx = 0.f, lx2 = 0.f;
        if (rr >= 0) {
            size_t base = (size_t)rr * MF + col0 + tn * 4;
            float4 u4 = *(const float4*)(uo_buf + base);
            float4 v4 = *(const float4*)(vo_buf + base);
            float uu[4] = {u4.x, u4.y, u4.z, u4.w};
            float vv[4] = {v4.x, v4.y, v4.z, v4.w};
            float un[4], vn[4];
#pragma unroll
            for (int j = 0; j < 4; j++) {
                float tt = acc[i][j] + uu[j];
                float av = fabsf(tt) - LAMBDv;
                float s = (av > 0.f) ? copysignf(av, tt) : 0.f;
                un[j] = tt - s;
                vn[j] = s;
                float d = s - vv[j];
                ldx += d * d;
                lx2 += s * s;
            }
            *(float4*)(un_buf + base) = make_float4(un[0], un[1], un[2], un[3]);
            *(float4*)(vn_buf + base) = make_float4(vn[0], vn[1], vn[2], vn[3]);
        }
        red_dx[lrow][tn] = ldx;
        red_x2[lrow][tn] = lx2;
    }
    __syncthreads();
    if (tid < BM) {
        int rr = rowidx[tid];
        if (rr >= 0) {
            float sdx = 0.f, sx2 = 0.f;
#pragma unroll
            for (int j = 0; j < 16; j++) { sdx += red_dx[tid][j]; sx2 += red_x2[tid][j]; }
            g_dx2p[rr * 16 + blockIdx.x] = sdx;
            g_x2p[rr * 16 + blockIdx.x] = sx2;
        }
    }
}

// ---------------- per-row convergence check; write v_sol into encoded output ----------------
__global__ void converge_kernel(float* __restrict__ enc, int pn) {
    int r = blockIdx.x;
    if (g_solved[r]) return;
    __shared__ int s_conv;
    if (threadIdx.x == 0) {
        float sdx = 0.f, sx2 = 0.f;
        for (int j = 0; j < 16; j++) { sdx += g_dx2p[r * 16 + j]; sx2 += g_x2p[r * 16 + j]; }
        int c = (sdx < TOL2 * sx2) ? 1 : 0;   // x2==0 -> false (matches nan/inf semantics)
        s_conv = c;
        if (c) g_solved[r] = 1;
    }
    __syncthreads();
    if (s_conv) {
        const float4* vrow = (const float4*)(g_v[pn] + (size_t)r * MF);
        float4* erow = (float4*)(enc + (size_t)r * MF);
        erow[threadIdx.x] = vrow[threadIdx.x];  // 256 threads * float4 = 1024 floats
    }
}

// ---------------- order-preserving compaction of active rows ----------------
__global__ void compact_kernel() {
    __shared__ int scnt[256];
    int t = threadIdx.x;
    int base = t * 4;
    int loc[4];
    int c = 0;
#pragma unroll
    for (int k = 0; k < 4; k++) {
        loc[k] = !g_solved[base + k];
        c += loc[k];
    }
    scnt[t] = c;
    __syncthreads();
    for (int off = 1; off < 256; off <<= 1) {
        int val = (t >= off) ? scnt[t - off] : 0;
        __syncthreads();
        scnt[t] += val;
        __syncthreads();
    }
    int pos = scnt[t] - c;  // exclusive prefix
#pragma unroll
    for (int k = 0; k < 4; k++) {
        if (loc[k]) g_idx[pos++] = base + k;
    }
    if (t == 255) g_nact = scnt[255];
}

// ---------------- decoded = encoded @ W : C[r,n] = sum_m E[r,m]*W[m,n] ----------------
__global__ void gemm_decode_kernel(const float* __restrict__ W, const float* __restrict__ enc,
                                   float* __restrict__ dec) {
    __shared__ float As[BK][BM];
    __shared__ float Bs[BK][BN];
    int tid = threadIdx.x;
    int row0 = blockIdx.y * BM, col0 = blockIdx.x * BN;
    int lr = tid >> 2, kq = tid & 3;
    int kr = tid >> 4, nq = tid & 15;
    int tm = tid >> 4, tn = tid & 15;
    float acc[4][4] = {};
    for (int k0 = 0; k0 < MF; k0 += BK) {
        float4 a4 = *(const float4*)(enc + (size_t)(row0 + lr) * MF + k0 + kq * 4);
        float4 b4 = *(const float4*)(W + (size_t)(k0 + kr) * NF + col0 + nq * 4);
        __syncthreads();
        As[kq * 4 + 0][lr] = a4.x; As[kq * 4 + 1][lr] = a4.y;
        As[kq * 4 + 2][lr] = a4.z; As[kq * 4 + 3][lr] = a4.w;
        *(float4*)&Bs[kr][nq * 4] = b4;
        __syncthreads();
#pragma unroll
        for (int kk = 0; kk < BK; kk++) {
            float4 av = *(const float4*)&As[kk][tm * 4];
            float4 bv = *(const float4*)&Bs[kk][tn * 4];
            float a[4] = {av.x, av.y, av.z, av.w};
            float b[4] = {bv.x, bv.y, bv.z, bv.w};
#pragma unroll
            for (int i = 0; i < 4; i++)
#pragma unroll
                for (int j = 0; j < 4; j++) acc[i][j] += a[i] * b[j];
        }
    }
#pragma unroll
    for (int i = 0; i < 4; i++) {
        float4 o = make_float4(acc[i][0], acc[i][1], acc[i][2], acc[i][3]);
        *(float4*)(dec + (size_t)(row0 + tm * 4 + i) * NF + col0 + tn * 4) = o;
    }
}

// ---------------- launch ----------------
extern "C" void kernel_launch(void* const* d_in, const int* in_sizes, int n_in,
                              void* d_out, int out_size) {
    const float* x = (const float*)d_in[0];      // (1024, 512)
    const float* w = (const float*)d_in[1];      // (1024, 512)
    const float* Minv = (const float*)d_in[2];   // (1024, 1024)
    float* out = (float*)d_out;
    float* enc = out;                 // 1024*1024
    float* dec = out + BATCH * MF;    // 1024*512

    init_kernel<<<BATCH * MF / 4 / 256, 256>>>(enc);
    gemm_nt_kernel<<<dim3(MF / BN, BATCH / BM), 256>>>(x, w);

    for (int it = 0; it < MAX_ITERS; it++) {
        int p = it & 1;
        gemm_update_kernel<<<dim3(MF / BN, BATCH / BM), 256>>>(Minv, p);
        converge_kernel<<<BATCH, 256>>>(enc, p ^ 1);
        compact_kernel<<<1, 256>>>();
    }

    gemm_decode_kernel<<<dim3(NF / BN, BATCH / BM), 256>>>(w, enc, dec);
}

// round 3
// speedup vs baseline: 1.0327x; 1.0327x over previous
#include <cuda_runtime.h>

#define BATCH 1024
#define MF 1024     // OUT_FEATURES
#define NF 512      // IN_FEATURES
#define LAMBDv 0.2f
#define TOL2 1e-8f  // (1e-4)^2
#define MAX_ITERS 100

#define BM 64
#define BN 64
#define BK 16

// ---------------- scratch (device globals; no allocation allowed) ----------------
__device__ __align__(256) float g_Adb[BATCH * MF];
__device__ __align__(256) float g_u[2][BATCH * MF];
__device__ __align__(256) float g_v[2][BATCH * MF];
__device__ __align__(256) float g_dx2p[BATCH * 16];
__device__ __align__(256) float g_x2p[BATCH * 16];
__device__ int g_solved[BATCH];
__device__ int g_idx[BATCH];
__device__ int g_nact;

// ---------------- init: zero state + encoded output, reset flags ----------------
__global__ void init_kernel(float* __restrict__ enc) {
    int i = blockIdx.x * blockDim.x + threadIdx.x;  // 0 .. BATCH*MF/4-1
    float4 z = make_float4(0.f, 0.f, 0.f, 0.f);
    ((float4*)g_u[0])[i] = z;
    ((float4*)g_v[0])[i] = z;
    ((float4*)enc)[i] = z;
    if (i < BATCH) { g_solved[i] = 0; g_idx[i] = i; }
    if (i == 0) g_nact = BATCH;
}

// ---------------- A_dot_b = x @ W^T : C[r,n] = sum_k X[r,k]*W[n,k] ----------------
__global__ void gemm_nt_kernel(const float* __restrict__ X, const float* __restrict__ W) {
    __shared__ float As[BK][BM];
    __shared__ float Bs[BK][BN];
    int tid = threadIdx.x;
    int row0 = blockIdx.y * BM, col0 = blockIdx.x * BN;
    int lr = tid >> 2, kq = tid & 3;
    int tm = tid >> 4, tn = tid & 15;
    float acc[4][4] = {};
    for (int k0 = 0; k0 < NF; k0 += BK) {
        float4 a4 = *(const float4*)(X + (size_t)(row0 + lr) * NF + k0 + kq * 4);
        float4 b4 = *(const float4*)(W + (size_t)(col0 + lr) * NF + k0 + kq * 4);
        __syncthreads();
        As[kq * 4 + 0][lr] = a4.x; As[kq * 4 + 1][lr] = a4.y;
        As[kq * 4 + 2][lr] = a4.z; As[kq * 4 + 3][lr] = a4.w;
        Bs[kq * 4 + 0][lr] = b4.x; Bs[kq * 4 + 1][lr] = b4.y;
        Bs[kq * 4 + 2][lr] = b4.z; Bs[kq * 4 + 3][lr] = b4.w;
        __syncthreads();
#pragma unroll
        for (int kk = 0; kk < BK; kk++) {
            float4 av = *(const float4*)&As[kk][tm * 4];
            float4 bv = *(const float4*)&Bs[kk][tn * 4];
            float a[4] = {av.x, av.y, av.z, av.w};
            float b[4] = {bv.x, bv.y, bv.z, bv.w};
#pragma unroll
            for (int i = 0; i < 4; i++)
#pragma unroll
                for (int j = 0; j < 4; j++) acc[i][j] += a[i] * b[j];
        }
    }
#pragma unroll
    for (int i = 0; i < 4; i++) {
        float4 o = make_float4(acc[i][0], acc[i][1], acc[i][2], acc[i][3]);
        *(float4*)(g_Adb + (size_t)(row0 + tm * 4 + i) * MF + col0 + tn * 4) = o;
    }
}

// ---------------- main iteration GEMM + fused ADMM epilogue ----------------
// xk = (A_dot_b + v - u) @ M_inv on active (compacted) rows only.
// reads parity p, writes parity p^1. Deterministic per-row norm partials.
__global__ void gemm_update_kernel(const float* __restrict__ Minv, int p) {
    int n_act = g_nact;
    int row0 = blockIdx.y * BM;
    if (row0 >= n_act) return;
    int col0 = blockIdx.x * BN;

    __shared__ float As[2][BK][BM];
    __shared__ float Bs[2][BK][BN];
    __shared__ int rowidx[BM];
    __shared__ float red_dx[BM][17];
    __shared__ float red_x2[BM][17];

    int tid = threadIdx.x;
    if (tid < BM) {
        int i = row0 + tid;
        rowidx[tid] = (i < n_act) ? g_idx[i] : -1;
    }
    __syncthreads();

    int lr = tid >> 2, kq = tid & 3;       // A-load mapping
    int kr = tid >> 4, nq = tid & 15;      // B-load mapping
    int tm = tid >> 4, tn = tid & 15;      // compute mapping

    int rA = rowidx[lr];
    const float* adbp = g_Adb + (size_t)rA * MF + kq * 4;
    const float* up = g_u[p] + (size_t)rA * MF + kq * 4;
    const float* vp = g_v[p] + (size_t)rA * MF + kq * 4;
    const float* bp = Minv + (size_t)kr * MF + col0 + nq * 4;

    float4 ra = make_float4(0, 0, 0, 0), rv = ra, ru = ra, rb;
    if (rA >= 0) {
        ra = *(const float4*)(adbp);
        rv = *(const float4*)(vp);
        ru = *(const float4*)(up);
    }
    rb = *(const float4*)(bp);
    As[0][kq * 4 + 0][lr] = ra.x + rv.x - ru.x;
    As[0][kq * 4 + 1][lr] = ra.y + rv.y - ru.y;
    As[0][kq * 4 + 2][lr] = ra.z + rv.z - ru.z;
    As[0][kq * 4 + 3][lr] = ra.w + rv.w - ru.w;
    *(float4*)&Bs[0][kr][nq * 4] = rb;
    __syncthreads();

    float acc[4][4] = {};
    const int NKT = MF / BK;  // 64
    for (int t = 0; t < NKT; t++) {
        int cb = t & 1;
        if (t + 1 < NKT) {
            int off = (t + 1) * BK;
            if (rA >= 0) {
                ra = *(const float4*)(adbp + off);
                rv = *(const float4*)(vp + off);
                ru = *(const float4*)(up + off);
            }
            rb = *(const float4*)(bp + (size_t)off * MF);
        }
#pragma unroll
        for (int kk = 0; kk < BK; kk++) {
            float4 av = *(const float4*)&As[cb][kk][tm * 4];
            float4 bv = *(const float4*)&Bs[cb][kk][tn * 4];
            float a[4] = {av.x, av.y, av.z, av.w};
            float b[4] = {bv.x, bv.y, bv.z, bv.w};
#pragma unroll
            for (int i = 0; i < 4; i++)
#pragma unroll
                for (int j = 0; j < 4; j++) acc[i][j] += a[i] * b[j];
        }
        if (t + 1 < NKT) {
            int nb = cb ^ 1;
            As[nb][kq * 4 + 0][lr] = ra.x + rv.x - ru.x;
            As[nb][kq * 4 + 1][lr] = ra.y + rv.y - ru.y;
            As[nb][kq * 4 + 2][lr] = ra.z + rv.z - ru.z;
            As[nb][kq * 4 + 3][lr] = ra.w + rv.w - ru.w;
            *(float4*)&Bs[nb][kr][nq * 4] = rb;
        }
        __syncthreads();
    }

    // fused ADMM epilogue
    const float* uo_buf = g_u[p];
    float* un_buf = g_u[p ^ 1];
    const float* vo_buf = g_v[p];
    float* vn_buf = g_v[p ^ 1];
#pragma unroll
    for (int i = 0; i < 4; i++) {
        int lrow = tm * 4 + i;
        int rr = rowidx[lrow];
        float ldx = 0.f, lx2 = 0.f;
        if (rr >= 0) {
            size_t base = (size_t)rr * MF + col0 + tn * 4;
            float4 u4 = *(const float4*)(uo_buf + base);
            float4 v4 = *(const float4*)(vo_buf + base);
            float uu[4] = {u4.x, u4.y, u4.z, u4.w};
            float vv[4] = {v4.x, v4.y, v4.z, v4.w};
            float un[4], vn[4];
#pragma unroll
            for (int j = 0; j < 4; j++) {
                float tt = acc[i][j] + uu[j];
                float av = fabsf(tt) - LAMBDv;
                float s = (av > 0.f) ? copysignf(av, tt) : 0.f;
                un[j] = tt - s;
                vn[j] = s;
                float d = s - vv[j];
                ldx += d * d;
                lx2 += s * s;
            }
            *(float4*)(un_buf + base) = make_float4(un[0], un[1], un[2], un[3]);
            *(float4*)(vn_buf + base) = make_float4(vn[0], vn[1], vn[2], vn[3]);
        }
        red_dx[lrow][tn] = ldx;
        red_x2[lrow][tn] = lx2;
    }
    __syncthreads();
    if (tid < BM) {
        int rr = rowidx[tid];
        if (rr >= 0) {
            float sdx = 0.f, sx2 = 0.f;
#pragma unroll
            for (int j = 0; j < 16; j++) { sdx += red_dx[tid][j]; sx2 += red_x2[tid][j]; }
            g_dx2p[rr * 16 + blockIdx.x] = sdx;
            g_x2p[rr * 16 + blockIdx.x] = sx2;
        }
    }
}

// ---------------- per-row convergence check; write v_sol into encoded output ----------------
__global__ void converge_kernel(float* __restrict__ enc, int pn) {
    int r = blockIdx.x;
    if (g_solved[r]) return;
    __shared__ int s_conv;
    if (threadIdx.x == 0) {
        float sdx = 0.f, sx2 = 0.f;
        for (int j = 0; j < 16; j++) { sdx += g_dx2p[r * 16 + j]; sx2 += g_x2p[r * 16 + j]; }
        int c = (sdx < TOL2 * sx2) ? 1 : 0;   // x2==0 -> false (matches nan/inf semantics)
        s_conv = c;
        if (c) g_solved[r] = 1;
    }
    __syncthreads();
    if (s_conv) {
        const float4* vrow = (const float4*)(g_v[pn] + (size_t)r * MF);
        float4* erow = (float4*)(enc + (size_t)r * MF);
        erow[threadIdx.x] = vrow[threadIdx.x];  // 256 threads * float4 = 1024 floats
    }
}

// ---------------- order-preserving compaction of active rows ----------------
__global__ void compact_kernel() {
    __shared__ int scnt[256];
    int t = threadIdx.x;
    int base = t * 4;
    int loc[4];
    int c = 0;
#pragma unroll
    for (int k = 0; k < 4; k++) {
        loc[k] = !g_solved[base + k];
        c += loc[k];
    }
    scnt[t] = c;
    __syncthreads();
    for (int off = 1; off < 256; off <<= 1) {
        int val = (t >= off) ? scnt[t - off] : 0;
        __syncthreads();
        scnt[t] += val;
        __syncthreads();
    }
    int pos = scnt[t] - c;  // exclusive prefix
#pragma unroll
    for (int k = 0; k < 4; k++) {
        if (loc[k]) g_idx[pos++] = base + k;
    }
    if (t == 255) g_nact = scnt[255];
}

// ---------------- decoded = encoded @ W : C[r,n] = sum_m E[r,m]*W[m,n] ----------------
__global__ void gemm_decode_kernel(const float* __restrict__ W, const float* __restrict__ enc,
                                   float* __restrict__ dec) {
    __shared__ float As[BK][BM];
    __shared__ float Bs[BK][BN];
    int tid = threadIdx.x;
    int row0 = blockIdx.y * BM, col0 = blockIdx.x * BN;
    int lr = tid >> 2, kq = tid & 3;
    int kr = tid >> 4, nq = tid & 15;
    int tm = tid >> 4, tn = tid & 15;
    float acc[4][4] = {};
    for (int k0 = 0; k0 < MF; k0 += BK) {
        float4 a4 = *(const float4*)(enc + (size_t)(row0 + lr) * MF + k0 + kq * 4);
        float4 b4 = *(const float4*)(W + (size_t)(k0 + kr) * NF + col0 + nq * 4);
        __syncthreads();
        As[kq * 4 + 0][lr] = a4.x; As[kq * 4 + 1][lr] = a4.y;
        As[kq * 4 + 2][lr] = a4.z; As[kq * 4 + 3][lr] = a4.w;
        *(float4*)&Bs[kr][nq * 4] = b4;
        __syncthreads();
#pragma unroll
        for (int kk = 0; kk < BK; kk++) {
            float4 av = *(const float4*)&As[kk][tm * 4];
            float4 bv = *(const float4*)&Bs[kk][tn * 4];
            float a[4] = {av.x, av.y, av.z, av.w};
            float b[4] = {bv.x, bv.y, bv.z, bv.w};
#pragma unroll
            for (int i = 0; i < 4; i++)
#pragma unroll
                for (int j = 0; j < 4; j++) acc[i][j] += a[i] * b[j];
        }
    }
#pragma unroll
    for (int i = 0; i < 4; i++) {
        float4 o = make_float4(acc[i][0], acc[i][1], acc[i][2], acc[i][3]);
        *(float4*)(dec + (size_t)(row0 + tm * 4 + i) * NF + col0 + tn * 4) = o;
    }
}

// ---------------- launch ----------------
extern "C" void kernel_launch(void* const* d_in, const int* in_sizes, int n_in,
                              void* d_out, int out_size) {
    const float* x = (const float*)d_in[0];      // (1024, 512)
    const float* w = (const float*)d_in[1];      // (1024, 512)
    const float* Minv = (const float*)d_in[2];   // (1024, 1024)
    float* out = (float*)d_out;
    float* enc = out;                 // 1024*1024
    float* dec = out + BATCH * MF;    // 1024*512

    init_kernel<<<BATCH * MF / 4 / 256, 256>>>(enc);
    gemm_nt_kernel<<<dim3(MF / BN, BATCH / BM), 256>>>(x, w);

    for (int it = 0; it < MAX_ITERS; it++) {
        int p = it & 1;
        gemm_update_kernel<<<dim3(MF / BN, BATCH / BM), 256>>>(Minv, p);
        converge_kernel<<<BATCH, 256>>>(enc, p ^ 1);
        compact_kernel<<<1, 256>>>();
    }

    gemm_decode_kernel<<<dim3(NF / BN, BATCH / BM), 256>>>(w, enc, dec);
}

// round 5
// speedup vs baseline: 1.6928x; 1.6392x over previous
#include <cuda_runtime.h>
#include <cuda_bf16.h>
#include <cstdint>

#define BATCH 1024
#define MF 1024
#define NF 512
#define LAMBDv 0.2f
#define TOL2 1e-8f
#define MAX_ITERS 100

// iteration GEMM tiling
#define KC 64
#define NCHUNK (MF / KC)            // 16
#define SROW 72                     // smem row stride in bf16 (144B, conflict-free)
#define TILEB (128 * SROW * 2)      // 18432 B per tile
#define STAGEB (4 * TILEB)          // Ahi, Alo, Bhi, Blo
#define DYN_SMEM (2 * STAGEB)       // 147456 B

// ---------------- device scratch ----------------
__device__ __align__(256) float g_Adb[BATCH * MF];
__device__ __align__(256) float g_u[BATCH * MF];
__device__ __align__(256) float g_v[BATCH * MF];
__device__ __align__(256) __nv_bfloat16 g_behi[2][BATCH * MF];
__device__ __align__(256) __nv_bfloat16 g_belo[2][BATCH * MF];
__device__ __align__(256) __nv_bfloat16 g_mThi[MF * MF];
__device__ __align__(256) __nv_bfloat16 g_mTlo[MF * MF];
__device__ float g_dx2p[BATCH * 8];
__device__ float g_x2p[BATCH * 8];
__device__ int g_solved[BATCH];
__device__ int g_stripe_done[8];

// ---------------- helpers ----------------
__device__ __forceinline__ uint32_t smem_u32(const void* p) {
    uint32_t a;
    asm("{ .reg .u64 t; cvta.to.shared.u64 t, %1; cvt.u32.u64 %0, t; }" : "=r"(a) : "l"(p));
    return a;
}
__device__ __forceinline__ unsigned lds32(uint32_t a) {
    unsigned v;
    asm volatile("ld.shared.b32 %0, [%1];" : "=r"(v) : "r"(a));
    return v;
}
__device__ __forceinline__ void cpa16(uint32_t dst, const void* src) {
    asm volatile("cp.async.cg.shared.global [%0], [%1], 16;" :: "r"(dst), "l"(src));
}
#define CP_COMMIT() asm volatile("cp.async.commit_group;" ::: "memory")
#define CP_WAIT(n)  asm volatile("cp.async.wait_group %0;" :: "n"(n) : "memory")

__device__ __forceinline__ void mma16816(float* c, const unsigned* a, const unsigned* b) {
    asm volatile(
        "mma.sync.aligned.m16n8k16.row.col.f32.bf16.bf16.f32 "
        "{%0,%1,%2,%3}, {%4,%5,%6,%7}, {%8,%9}, {%0,%1,%2,%3};"
        : "+f"(c[0]), "+f"(c[1]), "+f"(c[2]), "+f"(c[3])
        : "r"(a[0]), "r"(a[1]), "r"(a[2]), "r"(a[3]), "r"(b[0]), "r"(b[1]));
}
__device__ __forceinline__ void bsplit(float x, __nv_bfloat16& h, __nv_bfloat16& l) {
    h = __float2bfloat16(x);
    l = __float2bfloat16(x - __bfloat162float(h));
}

// ---------------- init ----------------
__global__ void init_kernel() {
    int i = blockIdx.x * blockDim.x + threadIdx.x;  // BATCH*MF/4
    float4 z = make_float4(0.f, 0.f, 0.f, 0.f);
    ((float4*)g_u)[i] = z;
    ((float4*)g_v)[i] = z;
    if (i < BATCH) g_solved[i] = 0;
    if (i < 8) g_stripe_done[i] = 0;
}

// ---------------- Minv -> transposed bf16 hi/lo split ----------------
__global__ void prep_minv(const float* __restrict__ Minv) {
    __shared__ float t[32][33];
    int bx = blockIdx.x * 32, by = blockIdx.y * 32;
    for (int i = threadIdx.y; i < 32; i += 8)
        t[i][threadIdx.x] = Minv[(size_t)(by + i) * MF + bx + threadIdx.x];
    __syncthreads();
    for (int i = threadIdx.y; i < 32; i += 8) {
        int n = bx + i, k = by + threadIdx.x;
        __nv_bfloat16 h, l;
        bsplit(t[threadIdx.x][i], h, l);  // Minv[k][n] -> MinvT[n][k]
        g_mThi[(size_t)n * MF + k] = h;
        g_mTlo[(size_t)n * MF + k] = l;
    }
}

// ---------------- A_dot_b = x @ W^T ; seeds beff[0] split (u=v=0) ----------------
__global__ void gemm_nt_kernel(const float* __restrict__ X, const float* __restrict__ W) {
    __shared__ float As[16][64];
    __shared__ float Bs[16][64];
    int tid = threadIdx.x;
    int row0 = blockIdx.y * 64, col0 = blockIdx.x * 64;
    int lr = tid >> 2, kq = tid & 3;
    int tm = tid >> 4, tn = tid & 15;
    float acc[4][4] = {};
    for (int k0 = 0; k0 < NF; k0 += 16) {
        float4 a4 = *(const float4*)(X + (size_t)(row0 + lr) * NF + k0 + kq * 4);
        float4 b4 = *(const float4*)(W + (size_t)(col0 + lr) * NF + k0 + kq * 4);
        __syncthreads();
        As[kq * 4 + 0][lr] = a4.x; As[kq * 4 + 1][lr] = a4.y;
        As[kq * 4 + 2][lr] = a4.z; As[kq * 4 + 3][lr] = a4.w;
        Bs[kq * 4 + 0][lr] = b4.x; Bs[kq * 4 + 1][lr] = b4.y;
        Bs[kq * 4 + 2][lr] = b4.z; Bs[kq * 4 + 3][lr] = b4.w;
        __syncthreads();
#pragma unroll
        for (int kk = 0; kk < 16; kk++) {
            float4 av = *(const float4*)&As[kk][tm * 4];
            float4 bv = *(const float4*)&Bs[kk][tn * 4];
            float a[4] = {av.x, av.y, av.z, av.w};
            float b[4] = {bv.x, bv.y, bv.z, bv.w};
#pragma unroll
            for (int i = 0; i < 4; i++)
#pragma unroll
                for (int j = 0; j < 4; j++) acc[i][j] += a[i] * b[j];
        }
    }
#pragma unroll
    for (int i = 0; i < 4; i++) {
        size_t base = (size_t)(row0 + tm * 4 + i) * MF + col0 + tn * 4;
        *(float4*)(g_Adb + base) = make_float4(acc[i][0], acc[i][1], acc[i][2], acc[i][3]);
#pragma unroll
        for (int j = 0; j < 4; j++) {
            __nv_bfloat16 h, l;
            bsplit(acc[i][j], h, l);
            g_behi[0][base + j] = h;
            g_belo[0][base + j] = l;
        }
    }
}

// ---------------- per-iteration mma.sync GEMM + fused ADMM epilogue ----------------
// xk[r,n] = sum_k beff[r,k] * MinvT[n,k]; bf16 hi/lo 3-pass into fp32 frags.
__global__ void __launch_bounds__(256, 1) admm_iter(int p) {
    if (g_stripe_done[blockIdx.y]) return;
    extern __shared__ __align__(16) char sraw[];
    __shared__ float red_dx[128][2];
    __shared__ float red_x2[128][2];

    const int tid = threadIdx.x;
    const int lane = tid & 31;
    const int w = tid >> 5;
    const int warp_m = w & 3;   // 4 warps x 32 rows
    const int warp_n = w >> 2;  // 2 warps x 64 cols
    const int row0 = blockIdx.y * 128;
    const int col0 = blockIdx.x * 128;
    const int pn = p ^ 1;

    const uint32_t sb = smem_u32(sraw);
    const __nv_bfloat16* srcs[4] = {g_behi[p], g_belo[p], g_mThi, g_mTlo};
    const int rbase[4] = {row0, row0, col0, col0};

    // per-thread cp.async coords: 4 x 16B per tile
    const int crow[4] = {(tid + 0) >> 3, (tid + 256) >> 3, (tid + 512) >> 3, (tid + 768) >> 3};
    const int cseg = tid & 7;

    // issue chunk 0
#pragma unroll
    for (int q = 0; q < 4; q++) {
        uint32_t tb = sb + q * TILEB;
        const __nv_bfloat16* src = srcs[q];
#pragma unroll
        for (int j = 0; j < 4; j++)
            cpa16(tb + crow[j] * (SROW * 2) + cseg * 16,
                  src + (size_t)(rbase[q] + crow[j]) * MF + cseg * 8);
    }
    CP_COMMIT();

    float c[2][8][4] = {};
    const uint32_t aoff = (lane >> 2) * (SROW * 2) + (lane & 3) * 4;
    const uint32_t boff = aoff;
    const int M0 = warp_m * 32;
    const int N0 = warp_n * 64;

    for (int t = 0; t < NCHUNK; t++) {
        int s = t & 1;
        if (t + 1 < NCHUNK) {
            int kb = (t + 1) * KC;
            uint32_t stb = sb + ((t + 1) & 1) * STAGEB;
#pragma unroll
            for (int q = 0; q < 4; q++) {
                uint32_t tb = stb + q * TILEB;
                const __nv_bfloat16* src = srcs[q];
#pragma unroll
                for (int j = 0; j < 4; j++)
                    cpa16(tb + crow[j] * (SROW * 2) + cseg * 16,
                          src + (size_t)(rbase[q] + crow[j]) * MF + kb + cseg * 8);
            }
            CP_COMMIT();
            CP_WAIT(1);
        } else {
            CP_WAIT(0);
        }
        __syncthreads();

        uint32_t Ah = sb + s * STAGEB;
        uint32_t Al = Ah + TILEB;
        uint32_t Bh = Al + TILEB;
        uint32_t Bl = Bh + TILEB;
#pragma unroll
        for (int kk = 0; kk < 4; kk++) {
            uint32_t K0b = kk * 32;  // 16 bf16 = 32B
            unsigned bh[8][2], bl[8][2];
#pragma unroll
            for (int fn = 0; fn < 8; fn++) {
                uint32_t ba = (uint32_t)(N0 + fn * 8) * (SROW * 2) + K0b + boff;
                bh[fn][0] = lds32(Bh + ba);
                bh[fn][1] = lds32(Bh + ba + 16);
                bl[fn][0] = lds32(Bl + ba);
                bl[fn][1] = lds32(Bl + ba + 16);
            }
#pragma unroll
            for (int fm = 0; fm < 2; fm++) {
                uint32_t aa = (uint32_t)(M0 + fm * 16) * (SROW * 2) + K0b + aoff;
                unsigned ah[4], al[4];
                ah[0] = lds32(Ah + aa);
                ah[1] = lds32(Ah + aa + 8 * SROW * 2);
                ah[2] = lds32(Ah + aa + 16);
                ah[3] = lds32(Ah + aa + 8 * SROW * 2 + 16);
                al[0] = lds32(Al + aa);
                al[1] = lds32(Al + aa + 8 * SROW * 2);
                al[2] = lds32(Al + aa + 16);
                al[3] = lds32(Al + aa + 8 * SROW * 2 + 16);
#pragma unroll
                for (int fn = 0; fn < 8; fn++) {
                    mma16816(c[fm][fn], ah, bh[fn]);
                    mma16816(c[fm][fn], ah, bl[fn]);
                    mma16816(c[fm][fn], al, bh[fn]);
                }
            }
        }
        __syncthreads();
    }

    // ---- fused ADMM epilogue on register fragments ----
    float pdx[2][2] = {}, px2[2][2] = {};
#pragma unroll
    for (int fm = 0; fm < 2; fm++) {
#pragma unroll
        for (int rs = 0; rs < 2; rs++) {
            int r = row0 + warp_m * 32 + fm * 16 + rs * 8 + (lane >> 2);
            int solved = g_solved[r];
            float ldx = 0.f, lx2 = 0.f;
#pragma unroll
            for (int fn = 0; fn < 8; fn++) {
                int cc = col0 + warp_n * 64 + fn * 8 + (lane & 3) * 2;
                size_t base = (size_t)r * MF + cc;
                float2 u2 = *(const float2*)(g_u + base);
                float2 v2 = *(const float2*)(g_v + base);
                float2 a2 = *(const float2*)(g_Adb + base);
                float uu[2] = {u2.x, u2.y}, vv[2] = {v2.x, v2.y}, aa[2] = {a2.x, a2.y};
                float un[2], vn[2];
#pragma unroll
                for (int jj = 0; jj < 2; jj++) {
                    float xk = c[fm][fn][rs * 2 + jj];
                    float tt = xk + uu[jj];
                    float av = fabsf(tt) - LAMBDv;
                    float sft = (av > 0.f) ? copysignf(av, tt) : 0.f;
                    if (!solved) {
                        un[jj] = tt - sft;
                        vn[jj] = sft;
                        float d = sft - vv[jj];
                        ldx += d * d;
                        lx2 += sft * sft;
                    } else {
                        un[jj] = uu[jj];
                        vn[jj] = vv[jj];
                    }
                }
                if (!solved) {
                    *(float2*)(g_u + base) = make_float2(un[0], un[1]);
                    *(float2*)(g_v + base) = make_float2(vn[0], vn[1]);
                }
                __nv_bfloat16 h0, l0, h1, l1;
                bsplit(aa[0] + vn[0] - un[0], h0, l0);
                bsplit(aa[1] + vn[1] - un[1], h1, l1);
                *(__nv_bfloat162*)(g_behi[pn] + base) = __halves2bfloat162(h0, h1);
                *(__nv_bfloat162*)(g_belo[pn] + base) = __halves2bfloat162(l0, l1);
            }
            pdx[fm][rs] = ldx;
            px2[fm][rs] = lx2;
        }
    }
    // reduce across the 4 column-lanes of each row (lane%4 varies cols only)
#pragma unroll
    for (int fm = 0; fm < 2; fm++) {
#pragma unroll
        for (int rs = 0; rs < 2; rs++) {
            float a = pdx[fm][rs], b = px2[fm][rs];
            a += __shfl_xor_sync(0xffffffffu, a, 1);
            a += __shfl_xor_sync(0xffffffffu, a, 2);
            b += __shfl_xor_sync(0xffffffffu, b, 1);
            b += __shfl_xor_sync(0xffffffffu, b, 2);
            if ((lane & 3) == 0) {
                int rl = warp_m * 32 + fm * 16 + rs * 8 + (lane >> 2);
                red_dx[rl][warp_n] = a;
                red_x2[rl][warp_n] = b;
            }
        }
    }
    __syncthreads();
    if (tid < 128) {
        int r = row0 + tid;
        g_dx2p[r * 8 + blockIdx.x] = red_dx[tid][0] + red_dx[tid][1];
        g_x2p[r * 8 + blockIdx.x] = red_x2[tid][0] + red_x2[tid][1];
    }
}

// ---------------- convergence flags + stripe-done ----------------
__global__ void converge_kernel() {
    int stripe = blockIdx.x;
    int r = stripe * 128 + threadIdx.x;
    __shared__ int cnt;
    if (threadIdx.x == 0) cnt = 0;
    __syncthreads();
    int slv = g_solved[r];
    if (!slv) {
        float sdx = 0.f, sx2 = 0.f;
#pragma unroll
        for (int j = 0; j < 8; j++) { sdx += g_dx2p[r * 8 + j]; sx2 += g_x2p[r * 8 + j]; }
        if (sdx < TOL2 * sx2) { g_solved[r] = 1; slv = 1; }
    }
    if (!slv) atomicAdd(&cnt, 1);
    __syncthreads();
    if (threadIdx.x == 0) g_stripe_done[stripe] = (cnt == 0);
}

// ---------------- enc = solved ? v : 0 ----------------
__global__ void finalize_enc(float* __restrict__ enc) {
    int i = blockIdx.x * blockDim.x + threadIdx.x;  // BATCH*MF/4
    int row = i / (MF / 4);
    float4 vv = ((const float4*)g_v)[i];
    float4 z = make_float4(0.f, 0.f, 0.f, 0.f);
    ((float4*)enc)[i] = g_solved[row] ? vv : z;
}

// ---------------- decoded = encoded @ W ----------------
__global__ void gemm_decode_kernel(const float* __restrict__ W, const float* __restrict__ enc,
                                   float* __restrict__ dec) {
    __shared__ float As[16][64];
    __shared__ float Bs[16][64];
    int tid = threadIdx.x;
    int row0 = blockIdx.y * 64, col0 = blockIdx.x * 64;
    int lr = tid >> 2, kq = tid & 3;
    int kr = tid >> 4, nq = tid & 15;
    int tm = tid >> 4, tn = tid & 15;
    float acc[4][4] = {};
    for (int k0 = 0; k0 < MF; k0 += 16) {
        float4 a4 = *(const float4*)(enc + (size_t)(row0 + lr) * MF + k0 + kq * 4);
        float4 b4 = *(const float4*)(W + (size_t)(k0 + kr) * NF + col0 + nq * 4);
        __syncthreads();
        As[kq * 4 + 0][lr] = a4.x; As[kq * 4 + 1][lr] = a4.y;
        As[kq * 4 + 2][lr] = a4.z; As[kq * 4 + 3][lr] = a4.w;
        *(float4*)&Bs[kr][nq * 4] = b4;
        __syncthreads();
#pragma unroll
        for (int kk = 0; kk < 16; kk++) {
            float4 av = *(const float4*)&As[kk][tm * 4];
            float4 bv = *(const float4*)&Bs[kk][tn * 4];
            float a[4] = {av.x, av.y, av.z, av.w};
            float b[4] = {bv.x, bv.y, bv.z, bv.w};
#pragma unroll
            for (int i = 0; i < 4; i++)
#pragma unroll
                for (int j = 0; j < 4; j++) acc[i][j] += a[i] * b[j];
        }
    }
#pragma unroll
    for (int i = 0; i < 4; i++) {
        float4 o = make_float4(acc[i][0], acc[i][1], acc[i][2], acc[i][3]);
        *(float4*)(dec + (size_t)(row0 + tm * 4 + i) * NF + col0 + tn * 4) = o;
    }
}

// ---------------- launch ----------------
extern "C" void kernel_launch(void* const* d_in, const int* in_sizes, int n_in,
                              void* d_out, int out_size) {
    const float* x = (const float*)d_in[0];      // (1024, 512)
    const float* w = (const float*)d_in[1];      // (1024, 512)
    const float* Minv = (const float*)d_in[2];   // (1024, 1024)
    float* out = (float*)d_out;
    float* enc = out;
    float* dec = out + BATCH * MF;

    static int attr_done = 0;
    if (!attr_done) {
        cudaFuncSetAttribute(admm_iter, cudaFuncAttributeMaxDynamicSharedMemorySize, DYN_SMEM);
        attr_done = 1;
    }

    init_kernel<<<BATCH * MF / 4 / 256, 256>>>();
    prep_minv<<<dim3(32, 32), dim3(32, 8)>>>(Minv);
    gemm_nt_kernel<<<dim3(MF / 64, BATCH / 64), 256>>>(x, w);

    for (int it = 0; it < MAX_ITERS; it++) {
        admm_iter<<<dim3(8, 8), 256, DYN_SMEM>>>(it & 1);
        converge_kernel<<<8, 128>>>();
    }

    finalize_enc<<<BATCH * MF / 4 / 256, 256>>>(enc);
    gemm_decode_kernel<<<dim3(NF / 64, BATCH / 64), 256>>>(w, enc, dec);
}

// round 6
// speedup vs baseline: 2.7013x; 1.5957x over previous
#include <cuda_runtime.h>
#include <cuda_bf16.h>
#include <cstdint>

#define BATCH 1024
#define MF 1024
#define NF 512
#define LAMBDv 0.2f
#define TOL2 1e-8f
#define MAX_ITERS 100

// iteration GEMM tiling: CTA tile 128(M) x 64(N), K chunks of 64
#define KC 64
#define NCHUNK (MF / KC)            // 16
#define SROW 72                     // smem row stride in bf16 (144B, ldmatrix conflict-free)
#define TILEB_A (128 * SROW * 2)    // 18432
#define TILEB_B (64 * SROW * 2)     // 9216
#define STAGEB (2 * TILEB_A + 2 * TILEB_B)  // 55296
#define DYN_SMEM (2 * STAGEB)       // 110592

// ---------------- device scratch ----------------
__device__ __align__(256) float g_Adb[BATCH * MF];
__device__ __align__(256) float g_u[BATCH * MF];
__device__ __align__(256) float g_v[BATCH * MF];
__device__ __align__(256) __nv_bfloat16 g_behi[2][BATCH * MF];
__device__ __align__(256) __nv_bfloat16 g_belo[2][BATCH * MF];
__device__ __align__(256) __nv_bfloat16 g_mThi[MF * MF];
__device__ __align__(256) __nv_bfloat16 g_mTlo[MF * MF];
__device__ float g_dx2p[BATCH * 16];
__device__ float g_x2p[BATCH * 16];
__device__ int g_solved[BATCH];
__device__ int g_stripe_done[8];

// ---------------- helpers ----------------
__device__ __forceinline__ uint32_t smem_u32(const void* p) {
    uint32_t a;
    asm("{ .reg .u64 t; cvta.to.shared.u64 t, %1; cvt.u32.u64 %0, t; }" : "=r"(a) : "l"(p));
    return a;
}
__device__ __forceinline__ void ldm_x4(unsigned* r, uint32_t addr) {
    asm volatile("ldmatrix.sync.aligned.m8n8.x4.shared.b16 {%0,%1,%2,%3}, [%4];"
        : "=r"(r[0]), "=r"(r[1]), "=r"(r[2]), "=r"(r[3]) : "r"(addr));
}
__device__ __forceinline__ void cpa16(uint32_t dst, const void* src) {
    asm volatile("cp.async.cg.shared.global [%0], [%1], 16;" :: "r"(dst), "l"(src));
}
#define CP_COMMIT() asm volatile("cp.async.commit_group;" ::: "memory")
#define CP_WAIT(n)  asm volatile("cp.async.wait_group %0;" :: "n"(n) : "memory")

__device__ __forceinline__ void mma16816(float* c, const unsigned* a, const unsigned* b) {
    asm volatile(
        "mma.sync.aligned.m16n8k16.row.col.f32.bf16.bf16.f32 "
        "{%0,%1,%2,%3}, {%4,%5,%6,%7}, {%8,%9}, {%0,%1,%2,%3};"
        : "+f"(c[0]), "+f"(c[1]), "+f"(c[2]), "+f"(c[3])
        : "r"(a[0]), "r"(a[1]), "r"(a[2]), "r"(a[3]), "r"(b[0]), "r"(b[1]));
}
__device__ __forceinline__ void bsplit(float x, __nv_bfloat16& h, __nv_bfloat16& l) {
    h = __float2bfloat16(x);
    l = __float2bfloat16(x - __bfloat162float(h));
}

// ---------------- init ----------------
__global__ void init_kernel() {
    int i = blockIdx.x * blockDim.x + threadIdx.x;  // BATCH*MF/4
    float4 z = make_float4(0.f, 0.f, 0.f, 0.f);
    ((float4*)g_u)[i] = z;
    ((float4*)g_v)[i] = z;
    if (i < BATCH) g_solved[i] = 0;
    if (i < 8) g_stripe_done[i] = 0;
}

// ---------------- Minv -> transposed bf16 hi/lo split ----------------
__global__ void prep_minv(const float* __restrict__ Minv) {
    __shared__ float t[32][33];
    int bx = blockIdx.x * 32, by = blockIdx.y * 32;
    for (int i = threadIdx.y; i < 32; i += 8)
        t[i][threadIdx.x] = Minv[(size_t)(by + i) * MF + bx + threadIdx.x];
    __syncthreads();
    for (int i = threadIdx.y; i < 32; i += 8) {
        int n = bx + i, k = by + threadIdx.x;
        __nv_bfloat16 h, l;
        bsplit(t[threadIdx.x][i], h, l);  // Minv[k][n] -> MinvT[n][k]
        g_mThi[(size_t)n * MF + k] = h;
        g_mTlo[(size_t)n * MF + k] = l;
    }
}

// ---------------- A_dot_b = x @ W^T ; seeds beff[0] split (u=v=0) ----------------
__global__ void gemm_nt_kernel(const float* __restrict__ X, const float* __restrict__ W) {
    __shared__ float As[16][64];
    __shared__ float Bs[16][64];
    int tid = threadIdx.x;
    int row0 = blockIdx.y * 64, col0 = blockIdx.x * 64;
    int lr = tid >> 2, kq = tid & 3;
    int tm = tid >> 4, tn = tid & 15;
    float acc[4][4] = {};
    for (int k0 = 0; k0 < NF; k0 += 16) {
        float4 a4 = *(const float4*)(X + (size_t)(row0 + lr) * NF + k0 + kq * 4);
        float4 b4 = *(const float4*)(W + (size_t)(col0 + lr) * NF + k0 + kq * 4);
        __syncthreads();
        As[kq * 4 + 0][lr] = a4.x; As[kq * 4 + 1][lr] = a4.y;
        As[kq * 4 + 2][lr] = a4.z; As[kq * 4 + 3][lr] = a4.w;
        Bs[kq * 4 + 0][lr] = b4.x; Bs[kq * 4 + 1][lr] = b4.y;
        Bs[kq * 4 + 2][lr] = b4.z; Bs[kq * 4 + 3][lr] = b4.w;
        __syncthreads();
#pragma unroll
        for (int kk = 0; kk < 16; kk++) {
            float4 av = *(const float4*)&As[kk][tm * 4];
            float4 bv = *(const float4*)&Bs[kk][tn * 4];
            float a[4] = {av.x, av.y, av.z, av.w};
            float b[4] = {bv.x, bv.y, bv.z, bv.w};
#pragma unroll
            for (int i = 0; i < 4; i++)
#pragma unroll
                for (int j = 0; j < 4; j++) acc[i][j] += a[i] * b[j];
        }
    }
#pragma unroll
    for (int i = 0; i < 4; i++) {
        size_t base = (size_t)(row0 + tm * 4 + i) * MF + col0 + tn * 4;
        *(float4*)(g_Adb + base) = make_float4(acc[i][0], acc[i][1], acc[i][2], acc[i][3]);
#pragma unroll
        for (int j = 0; j < 4; j++) {
            __nv_bfloat16 h, l;
            bsplit(acc[i][j], h, l);
            g_behi[0][base + j] = h;
            g_belo[0][base + j] = l;
        }
    }
}

// ---------------- per-iteration mma.sync GEMM + fused ADMM epilogue ----------------
// Tile 128(M) x 64(N); 8 warps as 4(M) x 2(N), warp tile 32x32.
// xk[r,n] = sum_k beff[r,k] * MinvT[n,k]; bf16 hi/lo 3-pass into fp32 frags.
__global__ void __launch_bounds__(256, 1) admm_iter(int p) {
    if (g_stripe_done[blockIdx.y]) return;
    extern __shared__ __align__(16) char sraw[];
    __shared__ float red_dx[128][2];
    __shared__ float red_x2[128][2];

    const int tid = threadIdx.x;
    const int lane = tid & 31;
    const int w = tid >> 5;
    const int warp_m = w & 3;   // 4 warps x 32 rows
    const int warp_n = w >> 2;  // 2 warps x 32 cols
    const int row0 = blockIdx.y * 128;
    const int col0 = blockIdx.x * 64;
    const int pn = p ^ 1;

    const uint32_t sb = smem_u32(sraw);

    // cp.async segment coords
    const int cs = tid & 7;   // 16B segment within 128B row-chunk
    // A rows: (tid + j*256) >> 3 for j=0..3 ; B rows: j=0..1

    // issue chunk 0
    {
        const __nv_bfloat16* ah = g_behi[p];
        const __nv_bfloat16* al = g_belo[p];
#pragma unroll
        for (int j = 0; j < 4; j++) {
            int row = (tid + j * 256) >> 3;
            uint32_t doff = (uint32_t)row * (SROW * 2) + cs * 16;
            const size_t soff = (size_t)(row0 + row) * MF + cs * 8;
            cpa16(sb + doff, ah + soff);
            cpa16(sb + TILEB_A + doff, al + soff);
        }
#pragma unroll
        for (int j = 0; j < 2; j++) {
            int row = (tid + j * 256) >> 3;
            uint32_t doff = (uint32_t)row * (SROW * 2) + cs * 16;
            const size_t soff = (size_t)(col0 + row) * MF + cs * 8;
            cpa16(sb + 2 * TILEB_A + doff, g_mThi + soff);
            cpa16(sb + 2 * TILEB_A + TILEB_B + doff, g_mTlo + soff);
        }
    }
    CP_COMMIT();

    float c[2][4][4] = {};
    // ldmatrix per-thread offsets
    const uint32_t a_off = (uint32_t)(warp_m * 32 + (lane & 15)) * (SROW * 2) + (lane >> 4) * 16;
    const uint32_t b_off = (uint32_t)(warp_n * 32 + (lane & 7) + ((lane >> 4) & 1) * 8) * (SROW * 2)
                         + ((lane >> 3) & 1) * 16;

    for (int t = 0; t < NCHUNK; t++) {
        int s = t & 1;
        if (t + 1 < NCHUNK) {
            int kb = (t + 1) * KC;
            uint32_t stb = sb + ((t + 1) & 1) * STAGEB;
            const __nv_bfloat16* ah = g_behi[p];
            const __nv_bfloat16* al = g_belo[p];
#pragma unroll
            for (int j = 0; j < 4; j++) {
                int row = (tid + j * 256) >> 3;
                uint32_t doff = (uint32_t)row * (SROW * 2) + cs * 16;
                const size_t soff = (size_t)(row0 + row) * MF + kb + cs * 8;
                cpa16(stb + doff, ah + soff);
                cpa16(stb + TILEB_A + doff, al + soff);
            }
#pragma unroll
            for (int j = 0; j < 2; j++) {
                int row = (tid + j * 256) >> 3;
                uint32_t doff = (uint32_t)row * (SROW * 2) + cs * 16;
                const size_t soff = (size_t)(col0 + row) * MF + kb + cs * 8;
                cpa16(stb + 2 * TILEB_A + doff, g_mThi + soff);
                cpa16(stb + 2 * TILEB_A + TILEB_B + doff, g_mTlo + soff);
            }
            CP_COMMIT();
            CP_WAIT(1);
        } else {
            CP_WAIT(0);
        }
        __syncthreads();

        const uint32_t Ah = sb + s * STAGEB;
        const uint32_t Al = Ah + TILEB_A;
        const uint32_t Bh = Ah + 2 * TILEB_A;
        const uint32_t Bl = Bh + TILEB_B;
#pragma unroll
        for (int kk = 0; kk < 4; kk++) {
            const uint32_t kb32 = kk * 32;  // 16 bf16 = 32B
            unsigned ah[2][4], al[2][4], bh[2][4], bl[2][4];
#pragma unroll
            for (int fm = 0; fm < 2; fm++) {
                uint32_t ao = a_off + (uint32_t)(fm * 16) * (SROW * 2) + kb32;
                ldm_x4(ah[fm], Ah + ao);
                ldm_x4(al[fm], Al + ao);
            }
#pragma unroll
            for (int pr = 0; pr < 2; pr++) {
                uint32_t bo = b_off + (uint32_t)(pr * 16) * (SROW * 2) + kb32;
                ldm_x4(bh[pr], Bh + bo);
                ldm_x4(bl[pr], Bl + bo);
            }
#pragma unroll
            for (int fm = 0; fm < 2; fm++)
#pragma unroll
                for (int fn = 0; fn < 4; fn++) {
                    const unsigned* ph = &bh[fn >> 1][(fn & 1) * 2];
                    const unsigned* pl = &bl[fn >> 1][(fn & 1) * 2];
                    mma16816(c[fm][fn], ah[fm], ph);
                    mma16816(c[fm][fn], ah[fm], pl);
                    mma16816(c[fm][fn], al[fm], ph);
                }
        }
        __syncthreads();
    }

    // ---- fused ADMM epilogue on register fragments ----
    float pdx[2][2] = {}, px2[2][2] = {};
#pragma unroll
    for (int fm = 0; fm < 2; fm++) {
#pragma unroll
        for (int rs = 0; rs < 2; rs++) {
            int r = row0 + warp_m * 32 + fm * 16 + rs * 8 + (lane >> 2);
            int solved = g_solved[r];
            float ldx = 0.f, lx2 = 0.f;
#pragma unroll
            for (int fn = 0; fn < 4; fn++) {
                int cc = col0 + warp_n * 32 + fn * 8 + (lane & 3) * 2;
                size_t base = (size_t)r * MF + cc;
                float2 u2 = *(const float2*)(g_u + base);
                float2 v2 = *(const float2*)(g_v + base);
                float2 a2 = *(const float2*)(g_Adb + base);
                float uu[2] = {u2.x, u2.y}, vv[2] = {v2.x, v2.y}, aa[2] = {a2.x, a2.y};
                float un[2], vn[2];
#pragma unroll
                for (int jj = 0; jj < 2; jj++) {
                    float xk = c[fm][fn][rs * 2 + jj];
                    float tt = xk + uu[jj];
                    float av = fabsf(tt) - LAMBDv;
                    float sft = (av > 0.f) ? copysignf(av, tt) : 0.f;
                    if (!solved) {
                        un[jj] = tt - sft;
                        vn[jj] = sft;
                        float d = sft - vv[jj];
                        ldx += d * d;
                        lx2 += sft * sft;
                    } else {
                        un[jj] = uu[jj];
                        vn[jj] = vv[jj];
                    }
                }
                if (!solved) {
                    *(float2*)(g_u + base) = make_float2(un[0], un[1]);
                    *(float2*)(g_v + base) = make_float2(vn[0], vn[1]);
                }
                __nv_bfloat16 h0, l0, h1, l1;
                bsplit(aa[0] + vn[0] - un[0], h0, l0);
                bsplit(aa[1] + vn[1] - un[1], h1, l1);
                *(__nv_bfloat162*)(g_behi[pn] + base) = __halves2bfloat162(h0, h1);
                *(__nv_bfloat162*)(g_belo[pn] + base) = __halves2bfloat162(l0, l1);
            }
            pdx[fm][rs] = ldx;
            px2[fm][rs] = lx2;
        }
    }
    // reduce across the 4 column-lanes of each row
#pragma unroll
    for (int fm = 0; fm < 2; fm++) {
#pragma unroll
        for (int rs = 0; rs < 2; rs++) {
            float a = pdx[fm][rs], b = px2[fm][rs];
            a += __shfl_xor_sync(0xffffffffu, a, 1);
            a += __shfl_xor_sync(0xffffffffu, a, 2);
            b += __shfl_xor_sync(0xffffffffu, b, 1);
            b += __shfl_xor_sync(0xffffffffu, b, 2);
            if ((lane & 3) == 0) {
                int rl = warp_m * 32 + fm * 16 + rs * 8 + (lane >> 2);
                red_dx[rl][warp_n] = a;
                red_x2[rl][warp_n] = b;
            }
        }
    }
    __syncthreads();
    if (tid < 128) {
        int r = row0 + tid;
        g_dx2p[r * 16 + blockIdx.x] = red_dx[tid][0] + red_dx[tid][1];
        g_x2p[r * 16 + blockIdx.x] = red_x2[tid][0] + red_x2[tid][1];
    }
}

// ---------------- convergence flags + stripe-done ----------------
__global__ void converge_kernel() {
    int stripe = blockIdx.x;
    int r = stripe * 128 + threadIdx.x;
    __shared__ int cnt;
    if (threadIdx.x == 0) cnt = 0;
    __syncthreads();
    int slv = g_solved[r];
    if (!slv) {
        float sdx = 0.f, sx2 = 0.f;
#pragma unroll
        for (int j = 0; j < 16; j++) { sdx += g_dx2p[r * 16 + j]; sx2 += g_x2p[r * 16 + j]; }
        if (sdx < TOL2 * sx2) { g_solved[r] = 1; slv = 1; }
    }
    if (!slv) atomicAdd(&cnt, 1);
    __syncthreads();
    if (threadIdx.x == 0) g_stripe_done[stripe] = (cnt == 0);
}

// ---------------- enc = solved ? v : 0 ----------------
__global__ void finalize_enc(float* __restrict__ enc) {
    int i = blockIdx.x * blockDim.x + threadIdx.x;  // BATCH*MF/4
    int row = i / (MF / 4);
    float4 vv = ((const float4*)g_v)[i];
    float4 z = make_float4(0.f, 0.f, 0.f, 0.f);
    ((float4*)enc)[i] = g_solved[row] ? vv : z;
}

// ---------------- decoded = encoded @ W ----------------
__global__ void gemm_decode_kernel(const float* __restrict__ W, const float* __restrict__ enc,
                                   float* __restrict__ dec) {
    __shared__ float As[16][64];
    __shared__ float Bs[16][64];
    int tid = threadIdx.x;
    int row0 = blockIdx.y * 64, col0 = blockIdx.x * 64;
    int lr = tid >> 2, kq = tid & 3;
    int kr = tid >> 4, nq = tid & 15;
    int tm = tid >> 4, tn = tid & 15;
    float acc[4][4] = {};
    for (int k0 = 0; k0 < MF; k0 += 16) {
        float4 a4 = *(const float4*)(enc + (size_t)(row0 + lr) * MF + k0 + kq * 4);
        float4 b4 = *(const float4*)(W + (size_t)(k0 + kr) * NF + col0 + nq * 4);
        __syncthreads();
        As[kq * 4 + 0][lr] = a4.x; As[kq * 4 + 1][lr] = a4.y;
        As[kq * 4 + 2][lr] = a4.z; As[kq * 4 + 3][lr] = a4.w;
        *(float4*)&Bs[kr][nq * 4] = b4;
        __syncthreads();
#pragma unroll
        for (int kk = 0; kk < 16; kk++) {
            float4 av = *(const float4*)&As[kk][tm * 4];
            float4 bv = *(const float4*)&Bs[kk][tn * 4];
            float a[4] = {av.x, av.y, av.z, av.w};
            float b[4] = {bv.x, bv.y, bv.z, bv.w};
#pragma unroll
            for (int i = 0; i < 4; i++)
#pragma unroll
                for (int j = 0; j < 4; j++) acc[i][j] += a[i] * b[j];
        }
    }
#pragma unroll
    for (int i = 0; i < 4; i++) {
        float4 o = make_float4(acc[i][0], acc[i][1], acc[i][2], acc[i][3]);
        *(float4*)(dec + (size_t)(row0 + tm * 4 + i) * NF + col0 + tn * 4) = o;
    }
}

// ---------------- launch ----------------
extern "C" void kernel_launch(void* const* d_in, const int* in_sizes, int n_in,
                              void* d_out, int out_size) {
    const float* x = (const float*)d_in[0];      // (1024, 512)
    const float* w = (const float*)d_in[1];      // (1024, 512)
    const float* Minv = (const float*)d_in[2];   // (1024, 1024)
    float* out = (float*)d_out;
    float* enc = out;
    float* dec = out + BATCH * MF;

    static int attr_done = 0;
    if (!attr_done) {
        cudaFuncSetAttribute(admm_iter, cudaFuncAttributeMaxDynamicSharedMemorySize, DYN_SMEM);
        attr_done = 1;
    }

    init_kernel<<<BATCH * MF / 4 / 256, 256>>>();
    prep_minv<<<dim3(32, 32), dim3(32, 8)>>>(Minv);
    gemm_nt_kernel<<<dim3(MF / 64, BATCH / 64), 256>>>(x, w);

    for (int it = 0; it < MAX_ITERS; it++) {
        admm_iter<<<dim3(16, 8), 256, DYN_SMEM>>>(it & 1);
        converge_kernel<<<8, 128>>>();
    }

    finalize_enc<<<BATCH * MF / 4 / 256, 256>>>(enc);
    gemm_decode_kernel<<<dim3(NF / 64, BATCH / 64), 256>>>(w, enc, dec);
}